// round 11
// baseline (speedup 1.0000x reference)
#include <cuda_runtime.h>
#include <cuda_bf16.h>
#include <math.h>
#include <stdint.h>

// ---------------------------------------------------------------------------
// RGCN 2-layer, gather-side restructuring.
// HARD RULE (empirical): __device__ globals must NEVER be referenced from
// host code; they are bound inside __global__ wrappers in device code only.
//
//   [h1 | xw] = x @ [root1 | W1cat] (+b1)    (bf16x3 mma GEMM; xw -> g_agg)
//   h1[dst]  += xw[src, r] * inv[r,dst]      (RED.v4 into L2-resident g_h1)
//   [oacc | hw] = relu(h1) @ [root2 | W2cat] (+b2)  (oacc -> g_cnt storage)
//   oacc[dst] += hw[src, r] * inv[r,dst]     (RED.v4 into L2-resident oacc)
//   d_out = log_softmax(relu(oacc))          (plain stores, k_final only)
//
// GEMM: A/B split to bf16 hi/lo ONCE at tile load, stored interleaved as
// uint2{hi,lo} (stride 36 uint2 => conflict-free LDS.64); inner loop is pure
// LDS.64 + mma.m16n8k16.bf16 (3 products: hh, hl, lh).
// ---------------------------------------------------------------------------

namespace {
constexpr int N_NODES = 100000;
constexpr int R = 16;
constexpr int D = 64;
constexpr int KBIG = R * D;  // 1024
}

__device__ int   g_cnt[R * N_NODES];
__device__ float g_inv[R * N_NODES];
__device__ float g_agg[(size_t)N_NODES * KBIG];
__device__ float g_h1[(size_t)N_NODES * D];

// ---------------------------------------------------------------------------
__global__ void k_zero_cnt() {
    int i = blockIdx.x * blockDim.x + threadIdx.x;
    if (i < R * N_NODES) g_cnt[i] = 0;
}

__global__ void k_count(const int* __restrict__ dst, const int* __restrict__ et, int E) {
    int i = blockIdx.x * blockDim.x + threadIdx.x;
    if (i < E) atomicAdd(&g_cnt[et[i] * N_NODES + dst[i]], 1);
}

__global__ void k_inv() {
    int i = blockIdx.x * blockDim.x + threadIdx.x;
    if (i < R * N_NODES) {
        int c = g_cnt[i];
        g_inv[i] = 1.0f / (float)(c > 0 ? c : 1);
    }
}

// ---------------------------------------------------------------------------
// bf16 helpers: pack (x,y) into bf16x2 hi word + residual lo word.
// ---------------------------------------------------------------------------
__device__ __forceinline__ uint32_t bf2_split(float x, float y, uint32_t& lo_out) {
    __nv_bfloat162 h = __floats2bfloat162_rn(x, y);
    float2 hf = __bfloat1622float2(h);
    __nv_bfloat162 l = __floats2bfloat162_rn(x - hf.x, y - hf.y);
    lo_out = *reinterpret_cast<uint32_t*>(&l);
    return *reinterpret_cast<uint32_t*>(&h);
}

__device__ __forceinline__ void mma_bf16(float* c, const uint32_t* a, const uint32_t* b) {
    asm volatile(
        "mma.sync.aligned.m16n8k16.row.col.f32.bf16.bf16.f32 "
        "{%0,%1,%2,%3}, {%4,%5,%6,%7}, {%8,%9}, {%0,%1,%2,%3};"
        : "+f"(c[0]), "+f"(c[1]), "+f"(c[2]), "+f"(c[3])
        : "r"(a[0]), "r"(a[1]), "r"(a[2]), "r"(a[3]), "r"(b[0]), "r"(b[1]));
}

// ---------------------------------------------------------------------------
// Fused GEMM body: C[N x (d1+d2)] = A[N x 64] @ [root(64 x d1) | Wcat(64 x d2)]
// Root cols get +bias -> outRoot (row stride d1). Wcat cols -> outW (stride d2).
// Wcat column w maps to W[(w/dout)*64*dout + k*dout + (w%dout)]  (W is (R,64,dout)).
// 1-D grid: rb = bid % rowBlocks, cb = bid / rowBlocks.
// BM=64, BN=64, K=64. 256 threads, 8 warps (4m x 2n), warp tile 16x32.
// Smem: Ax[row][pair], Bx[col][pair]; pair = k/2; uint2 = {hi bf16x2, lo bf16x2}.
// Stride 36 uint2 (32 payload + 4 pad): 36 mod 16 == 4 -> conflict-free LDS.64.
// ---------------------------------------------------------------------------
namespace {
constexpr int SP = 36;
}

__device__ __forceinline__ void gemm_body(
    const float* __restrict__ A, const float* __restrict__ root,
    const float* __restrict__ W, const float* __restrict__ bias,
    float* __restrict__ outRoot, float* __restrict__ outW,
    int d1, int d2, int dout, int reluA, int rowBlocks) {
    __shared__ uint2 Ax[64 * SP];   // 18.4 KB
    __shared__ uint2 Bx[64 * SP];   // 18.4 KB

    const int tid = threadIdx.x;
    const int rb = blockIdx.x % rowBlocks;
    const int cb = blockIdx.x / rowBlocks;
    const int dtot = d1 + d2;

    // ---- load A tile (64 x 64) and split to bf16 hi/lo pairs ----
#pragma unroll
    for (int i = 0; i < 4; ++i) {
        int idx = tid + i * 256;          // float4 index
        int row = idx >> 4, c4 = idx & 15;
        int grow = rb * 64 + row;
        float4 v = make_float4(0.f, 0.f, 0.f, 0.f);
        if (grow < N_NODES)
            v = reinterpret_cast<const float4*>(A)[(size_t)grow * 16 + c4];
        if (reluA) {
            v.x = fmaxf(v.x, 0.f); v.y = fmaxf(v.y, 0.f);
            v.z = fmaxf(v.z, 0.f); v.w = fmaxf(v.w, 0.f);
        }
        uint32_t l01, l23;
        uint32_t h01 = bf2_split(v.x, v.y, l01);
        uint32_t h23 = bf2_split(v.z, v.w, l23);
        Ax[row * SP + 2 * c4]     = make_uint2(h01, l01);
        Ax[row * SP + 2 * c4 + 1] = make_uint2(h23, l23);
    }
    // ---- load B tile (64k x 64 cols) transposed into Bx[col][pair] ----
#pragma unroll
    for (int i = 0; i < 8; ++i) {
        int idx = tid + i * 256;          // (col, pair) index: 64*32 = 2048
        int c = idx >> 5, k2 = idx & 31;
        int gc = cb * 64 + c;
        int k0 = k2 * 2;
        float f0 = 0.f, f1 = 0.f;
        if (gc < d1) {
            f0 = root[(size_t)k0 * d1 + gc];
            f1 = root[(size_t)(k0 + 1) * d1 + gc];
        } else if (gc < dtot) {
            int w = gc - d1;
            int r = w / dout, j = w - r * dout;
            f0 = W[((size_t)r * 64 + k0) * dout + j];
            f1 = W[((size_t)r * 64 + k0 + 1) * dout + j];
        }
        uint32_t lo;
        uint32_t hi = bf2_split(f0, f1, lo);
        Bx[c * SP + k2] = make_uint2(hi, lo);
    }
    __syncthreads();

    const int wid = tid >> 5, lane = tid & 31;
    const int g = lane >> 2, tg = lane & 3;
    const int wm = (wid & 3) * 16;    // warp row offset (4 warps in m)
    const int wn = (wid >> 2) * 32;   // warp col offset (2 warps in n)

    float acc[4][4];
#pragma unroll
    for (int nt = 0; nt < 4; ++nt)
#pragma unroll
        for (int q = 0; q < 4; ++q) acc[nt][q] = 0.f;

#pragma unroll
    for (int ks = 0; ks < 4; ++ks) {
        const int p0 = ks * 8;            // pair offset (16 k per step)
        uint2 A0 = Ax[(wm + g)     * SP + p0 + tg];
        uint2 A1 = Ax[(wm + g + 8) * SP + p0 + tg];
        uint2 A2 = Ax[(wm + g)     * SP + p0 + tg + 4];
        uint2 A3 = Ax[(wm + g + 8) * SP + p0 + tg + 4];
        uint32_t ah[4] = {A0.x, A1.x, A2.x, A3.x};
        uint32_t al[4] = {A0.y, A1.y, A2.y, A3.y};
        uint32_t bh[4][2], bl[4][2];
#pragma unroll
        for (int nt = 0; nt < 4; ++nt) {
            int c0 = wn + nt * 8 + g;
            uint2 B0 = Bx[c0 * SP + p0 + tg];
            uint2 B1 = Bx[c0 * SP + p0 + tg + 4];
            bh[nt][0] = B0.x; bh[nt][1] = B1.x;
            bl[nt][0] = B0.y; bl[nt][1] = B1.y;
        }
#pragma unroll
        for (int nt = 0; nt < 4; ++nt) {
            mma_bf16(acc[nt], ah, bh[nt]);   // hi*hi
            mma_bf16(acc[nt], ah, bl[nt]);   // hi*lo
            mma_bf16(acc[nt], al, bh[nt]);   // lo*hi
        }
    }

    // ---- epilogue: root cols (+bias) -> outRoot; W cols -> outW ----
#pragma unroll
    for (int nt = 0; nt < 4; ++nt) {
        int col = wn + nt * 8 + 2 * tg;
        int gc = cb * 64 + col;
        int r0 = rb * 64 + wm + g;
        int r1 = r0 + 8;
        float2 v0 = make_float2(acc[nt][0], acc[nt][1]);
        float2 v1 = make_float2(acc[nt][2], acc[nt][3]);
        if (gc < d1) {
            float bx = bias[gc], by = bias[gc + 1];
            v0.x += bx; v0.y += by; v1.x += bx; v1.y += by;
            if (r0 < N_NODES)
                *reinterpret_cast<float2*>(&outRoot[(size_t)r0 * d1 + gc]) = v0;
            if (r1 < N_NODES)
                *reinterpret_cast<float2*>(&outRoot[(size_t)r1 * d1 + gc]) = v1;
        } else if (gc < dtot) {
            int w = gc - d1;
            if (r0 < N_NODES)
                *reinterpret_cast<float2*>(&outW[(size_t)r0 * d2 + w]) = v0;
            if (r1 < N_NODES)
                *reinterpret_cast<float2*>(&outW[(size_t)r1 * d2 + w]) = v1;
        }
    }
}

// Layer 1: [h1 | xw] = x @ [root1 | W1cat] + b1. Globals bound in device code.
__global__ void __launch_bounds__(256) k_gemm_l1(
    const float* __restrict__ x, const float* __restrict__ W1,
    const float* __restrict__ root1, const float* __restrict__ b1,
    int rowBlocks) {
    gemm_body(x, root1, W1, b1, g_h1, g_agg, 64, 1024, 64, 0, rowBlocks);
}

// Layer 2: [oacc | hw] = relu(h1) @ [root2 | W2cat] + b2 (oacc in g_cnt storage).
__global__ void __launch_bounds__(256) k_gemm_l2(
    const float* __restrict__ W2, const float* __restrict__ root2,
    const float* __restrict__ b2, int rowBlocks) {
    gemm_body(g_h1, root2, W2, b2, reinterpret_cast<float*>(g_cnt), g_agg,
              16, 256, 16, 1, rowBlocks);
}

// ---------------------------------------------------------------------------
__device__ __forceinline__ void red_add_v4(float* addr, float4 v) {
    asm volatile("red.global.add.v4.f32 [%0], {%1, %2, %3, %4};"
                 :: "l"(addr), "f"(v.x), "f"(v.y), "f"(v.z), "f"(v.w)
                 : "memory");
}

// 16 threads/edge: gather xw[src, r] (64 floats from g_agg), weight,
// RED into h1[dst] (L2-resident; holds the root term from the GEMM).
__global__ void k_scatter1(const int* __restrict__ src, const int* __restrict__ dst,
                           const int* __restrict__ et, int E) {
    long long gid = (long long)blockIdx.x * blockDim.x + threadIdx.x;
    int e = (int)(gid >> 4);
    int lane = (int)(gid & 15);
    if (e >= E) return;
    int s = __ldg(src + e), d = __ldg(dst + e), r = __ldg(et + e);
    float w = g_inv[r * N_NODES + d];
    float4 v = *reinterpret_cast<const float4*>(
        &g_agg[(size_t)s * KBIG + r * 64 + lane * 4]);
    red_add_v4(&g_h1[(size_t)d * D + lane * 4],
               make_float4(v.x * w, v.y * w, v.z * w, v.w * w));
}

// 4 threads/edge: gather hw[src, r] (16 floats from g_agg head), weight,
// RED into oacc[dst] = (float*)g_cnt (L2-resident; holds the root term).
__global__ void k_scatter2(const int* __restrict__ src, const int* __restrict__ dst,
                           const int* __restrict__ et, int E) {
    long long gid = (long long)blockIdx.x * blockDim.x + threadIdx.x;
    int e = (int)(gid >> 2);
    int lane = (int)(gid & 3);
    if (e >= E) return;
    int s = __ldg(src + e), d = __ldg(dst + e), r = __ldg(et + e);
    float w = g_inv[r * N_NODES + d];
    float4 v = *reinterpret_cast<const float4*>(
        &g_agg[(size_t)s * 256 + r * 16 + lane * 4]);
    red_add_v4(&reinterpret_cast<float*>(g_cnt)[(size_t)d * 16 + lane * 4],
               make_float4(v.x * w, v.y * w, v.z * w, v.w * w));
}

// relu + log_softmax over 16 classes; reads oacc (g_cnt storage), writes d_out
// with plain stores only. One thread per row.
__global__ void k_final(float* __restrict__ out) {
    int row = blockIdx.x * blockDim.x + threadIdx.x;
    if (row >= N_NODES) return;
    float v[16];
    const float4* p = reinterpret_cast<const float4*>(
        &reinterpret_cast<const float*>(g_cnt)[(size_t)row * 16]);
#pragma unroll
    for (int q = 0; q < 4; ++q) {
        float4 t = p[q];
        v[q * 4 + 0] = fmaxf(t.x, 0.f);
        v[q * 4 + 1] = fmaxf(t.y, 0.f);
        v[q * 4 + 2] = fmaxf(t.z, 0.f);
        v[q * 4 + 3] = fmaxf(t.w, 0.f);
    }
    float m = -1e30f;
#pragma unroll
    for (int j = 0; j < 16; ++j) m = fmaxf(m, v[j]);
    float s = 0.f;
#pragma unroll
    for (int j = 0; j < 16; ++j) s += expf(v[j] - m);
    float ls = m + logf(s);
    float4* q4 = reinterpret_cast<float4*>(&out[(size_t)row * 16]);
#pragma unroll
    for (int q = 0; q < 4; ++q)
        q4[q] = make_float4(v[q * 4 + 0] - ls, v[q * 4 + 1] - ls,
                            v[q * 4 + 2] - ls, v[q * 4 + 3] - ls);
}

// ---------------------------------------------------------------------------
extern "C" void kernel_launch(void* const* d_in, const int* in_sizes, int n_in,
                              void* d_out, int out_size) {
    const float* x     = (const float*)d_in[0];
    const int*   ei    = (const int*)d_in[1];
    const int*   et    = (const int*)d_in[2];
    const float* W1    = (const float*)d_in[3];
    const float* root1 = (const float*)d_in[4];
    const float* b1    = (const float*)d_in[5];
    const float* W2    = (const float*)d_in[6];
    const float* root2 = (const float*)d_in[7];
    const float* b2    = (const float*)d_in[8];
    float* out = (float*)d_out;

    const int E = in_sizes[2];
    const int* src = ei;
    const int* dst = ei + E;

    const int t = 256;
    const int gRN = (R * N_NODES + t - 1) / t;
    const int rowBlocks = (N_NODES + 63) / 64;
    const int gS1 = (int)(((long long)E * 16 + t - 1) / t);
    const int gS2 = (int)(((long long)E * 4 + t - 1) / t);

    // counts + inverse (shared by both layers); g_cnt is dead after k_inv
    k_zero_cnt<<<gRN, t>>>();
    k_count<<<(E + t - 1) / t, t>>>(dst, et, E);
    k_inv<<<gRN, t>>>();

    // layer 1: [h1 | xw] = x @ [root1 | W1cat] + b1; scatter messages into h1
    k_gemm_l1<<<rowBlocks * 17, t>>>(x, W1, root1, b1, rowBlocks);
    k_scatter1<<<gS1, t>>>(src, dst, et, E);

    // layer 2: [oacc | hw] = relu(h1) @ [root2 | W2cat] + b2 (oacc in g_cnt)
    k_gemm_l2<<<rowBlocks * 5, t>>>(W2, root2, b2, rowBlocks);
    k_scatter2<<<gS2, t>>>(src, dst, et, E);
    k_final<<<(N_NODES + t - 1) / t, t>>>(out);
}

// round 12
// speedup vs baseline: 1.6669x; 1.6669x over previous
#include <cuda_runtime.h>
#include <cuda_bf16.h>
#include <math.h>
#include <stdint.h>

// ---------------------------------------------------------------------------
// RGCN 2-layer, gather-side restructuring.
// HARD RULE (empirical): __device__ globals must NEVER be referenced from
// host code; they are bound inside __global__ wrappers in device code only.
//
//   [h1 | xw] = x @ [root1 | W1cat] (+b1)    (bf16x3 mma GEMM; xw -> g_agg)
//   h1[dst]  += xw[src, r] * inv[r,dst]      (RED.v4 into L2-resident g_h1)
//   [oacc | hw] = relu(h1) @ [root2 | W2cat] (+b2)  (oacc -> g_cnt storage)
//   oacc[dst] += hw[src, r] * inv[r,dst]     (RED.v4 into L2-resident oacc)
//   d_out = log_softmax(relu(oacc))          (plain stores, k_final only)
//
// GEMM: A/B split to bf16 hi/lo ONCE at tile load, stored interleaved as
// uint2{hi,lo} (stride 36 uint2 => conflict-free LDS.64 in the mma loop);
// inner loop is pure LDS.64 + mma.m16n8k16.bf16 (products hh, hl, lh).
// R12 fix vs R11: B-tile global loads are column-fast (coalesced), not k-fast.
// ---------------------------------------------------------------------------

namespace {
constexpr int N_NODES = 100000;
constexpr int R = 16;
constexpr int D = 64;
constexpr int KBIG = R * D;  // 1024
}

__device__ int   g_cnt[R * N_NODES];
__device__ float g_inv[R * N_NODES];
__device__ float g_agg[(size_t)N_NODES * KBIG];
__device__ float g_h1[(size_t)N_NODES * D];

// ---------------------------------------------------------------------------
__global__ void k_zero_cnt() {
    int i = blockIdx.x * blockDim.x + threadIdx.x;
    if (i < R * N_NODES) g_cnt[i] = 0;
}

__global__ void k_count(const int* __restrict__ dst, const int* __restrict__ et, int E) {
    int i = blockIdx.x * blockDim.x + threadIdx.x;
    if (i < E) atomicAdd(&g_cnt[et[i] * N_NODES + dst[i]], 1);
}

__global__ void k_inv() {
    int i = blockIdx.x * blockDim.x + threadIdx.x;
    if (i < R * N_NODES) {
        int c = g_cnt[i];
        g_inv[i] = 1.0f / (float)(c > 0 ? c : 1);
    }
}

// ---------------------------------------------------------------------------
// bf16 helpers: pack (x,y) into bf16x2 hi word + residual lo word.
// ---------------------------------------------------------------------------
__device__ __forceinline__ uint32_t bf2_split(float x, float y, uint32_t& lo_out) {
    __nv_bfloat162 h = __floats2bfloat162_rn(x, y);
    float2 hf = __bfloat1622float2(h);
    __nv_bfloat162 l = __floats2bfloat162_rn(x - hf.x, y - hf.y);
    lo_out = *reinterpret_cast<uint32_t*>(&l);
    return *reinterpret_cast<uint32_t*>(&h);
}

__device__ __forceinline__ void mma_bf16(float* c, const uint32_t* a, const uint32_t* b) {
    asm volatile(
        "mma.sync.aligned.m16n8k16.row.col.f32.bf16.bf16.f32 "
        "{%0,%1,%2,%3}, {%4,%5,%6,%7}, {%8,%9}, {%0,%1,%2,%3};"
        : "+f"(c[0]), "+f"(c[1]), "+f"(c[2]), "+f"(c[3])
        : "r"(a[0]), "r"(a[1]), "r"(a[2]), "r"(a[3]), "r"(b[0]), "r"(b[1]));
}

// ---------------------------------------------------------------------------
// Fused GEMM body: C[N x (d1+d2)] = A[N x 64] @ [root(64 x d1) | Wcat(64 x d2)]
// Root cols get +bias -> outRoot (row stride d1). Wcat cols -> outW (stride d2).
// Wcat column w maps to W[(w/dout)*64*dout + k*dout + (w%dout)]  (W is (R,64,dout)).
// 1-D grid: rb = bid % rowBlocks, cb = bid / rowBlocks (consecutive blocks
// share the B tile -> L2 reuse).
// BM=64, BN=64, K=64. 256 threads, 8 warps (4m x 2n), warp tile 16x32.
// Smem: Ax[row][pair], Bx[col][pair]; pair = k/2; uint2 = {hi bf16x2, lo bf16x2}.
// Stride 36 uint2: fragment LDS.64 conflict-free (verified by R11 correctness).
// ---------------------------------------------------------------------------
namespace {
constexpr int SP = 36;
}

__device__ __forceinline__ void gemm_body(
    const float* __restrict__ A, const float* __restrict__ root,
    const float* __restrict__ W, const float* __restrict__ bias,
    float* __restrict__ outRoot, float* __restrict__ outW,
    int d1, int d2, int dout, int reluA, int rowBlocks) {
    __shared__ uint2 Ax[64 * SP];   // 18.4 KB
    __shared__ uint2 Bx[64 * SP];   // 18.4 KB

    const int tid = threadIdx.x;
    const int rb = blockIdx.x % rowBlocks;
    const int cb = blockIdx.x / rowBlocks;
    const int dtot = d1 + d2;

    // ---- load A tile (64 x 64) coalesced, split to bf16 hi/lo pairs ----
#pragma unroll
    for (int i = 0; i < 4; ++i) {
        int idx = tid + i * 256;          // float4 index
        int row = idx >> 4, c4 = idx & 15;
        int grow = rb * 64 + row;
        float4 v = make_float4(0.f, 0.f, 0.f, 0.f);
        if (grow < N_NODES)
            v = reinterpret_cast<const float4*>(A)[(size_t)grow * 16 + c4];
        if (reluA) {
            v.x = fmaxf(v.x, 0.f); v.y = fmaxf(v.y, 0.f);
            v.z = fmaxf(v.z, 0.f); v.w = fmaxf(v.w, 0.f);
        }
        uint32_t l01, l23;
        uint32_t h01 = bf2_split(v.x, v.y, l01);
        uint32_t h23 = bf2_split(v.z, v.w, l23);
        *reinterpret_cast<uint4*>(&Ax[row * SP + 2 * c4]) =
            make_uint4(h01, l01, h23, l23);
    }
    // ---- load B tile (64k x 64 cols): COLUMN-fast (coalesced), store
    //      transposed into Bx[col][pair] ----
#pragma unroll
    for (int i = 0; i < 8; ++i) {
        int idx = tid + i * 256;          // p * 64 + c  (c fast -> coalesced)
        int p = idx >> 6, c = idx & 63;
        int gc = cb * 64 + c;
        int k0 = p * 2;
        float f0 = 0.f, f1 = 0.f;
        if (gc < d1) {
            f0 = root[(size_t)k0 * d1 + gc];
            f1 = root[(size_t)(k0 + 1) * d1 + gc];
        } else if (gc < dtot) {
            int w = gc - d1;
            int r = w / dout, j = w - r * dout;
            f0 = W[((size_t)r * 64 + k0) * dout + j];
            f1 = W[((size_t)r * 64 + k0 + 1) * dout + j];
        }
        uint32_t lo;
        uint32_t hi = bf2_split(f0, f1, lo);
        Bx[c * SP + p] = make_uint2(hi, lo);
    }
    __syncthreads();

    const int wid = tid >> 5, lane = tid & 31;
    const int g = lane >> 2, tg = lane & 3;
    const int wm = (wid & 3) * 16;    // warp row offset (4 warps in m)
    const int wn = (wid >> 2) * 32;   // warp col offset (2 warps in n)

    float acc[4][4];
#pragma unroll
    for (int nt = 0; nt < 4; ++nt)
#pragma unroll
        for (int q = 0; q < 4; ++q) acc[nt][q] = 0.f;

#pragma unroll
    for (int ks = 0; ks < 4; ++ks) {
        const int p0 = ks * 8;            // pair offset (16 k per step)
        uint2 A0 = Ax[(wm + g)     * SP + p0 + tg];
        uint2 A1 = Ax[(wm + g + 8) * SP + p0 + tg];
        uint2 A2 = Ax[(wm + g)     * SP + p0 + tg + 4];
        uint2 A3 = Ax[(wm + g + 8) * SP + p0 + tg + 4];
        uint32_t ah[4] = {A0.x, A1.x, A2.x, A3.x};
        uint32_t al[4] = {A0.y, A1.y, A2.y, A3.y};
        uint32_t bh[4][2], bl[4][2];
#pragma unroll
        for (int nt = 0; nt < 4; ++nt) {
            int c0 = wn + nt * 8 + g;
            uint2 B0 = Bx[c0 * SP + p0 + tg];
            uint2 B1 = Bx[c0 * SP + p0 + tg + 4];
            bh[nt][0] = B0.x; bh[nt][1] = B1.x;
            bl[nt][0] = B0.y; bl[nt][1] = B1.y;
        }
#pragma unroll
        for (int nt = 0; nt < 4; ++nt) {
            mma_bf16(acc[nt], ah, bh[nt]);   // hi*hi
            mma_bf16(acc[nt], ah, bl[nt]);   // hi*lo
            mma_bf16(acc[nt], al, bh[nt]);   // lo*hi
        }
    }

    // ---- epilogue: root cols (+bias) -> outRoot; W cols -> outW ----
#pragma unroll
    for (int nt = 0; nt < 4; ++nt) {
        int col = wn + nt * 8 + 2 * tg;
        int gc = cb * 64 + col;
        int r0 = rb * 64 + wm + g;
        int r1 = r0 + 8;
        float2 v0 = make_float2(acc[nt][0], acc[nt][1]);
        float2 v1 = make_float2(acc[nt][2], acc[nt][3]);
        if (gc < d1) {
            float bx = bias[gc], by = bias[gc + 1];
            v0.x += bx; v0.y += by; v1.x += bx; v1.y += by;
            if (r0 < N_NODES)
                *reinterpret_cast<float2*>(&outRoot[(size_t)r0 * d1 + gc]) = v0;
            if (r1 < N_NODES)
                *reinterpret_cast<float2*>(&outRoot[(size_t)r1 * d1 + gc]) = v1;
        } else if (gc < dtot) {
            int w = gc - d1;
            if (r0 < N_NODES)
                *reinterpret_cast<float2*>(&outW[(size_t)r0 * d2 + w]) = v0;
            if (r1 < N_NODES)
                *reinterpret_cast<float2*>(&outW[(size_t)r1 * d2 + w]) = v1;
        }
    }
}

// Layer 1: [h1 | xw] = x @ [root1 | W1cat] + b1. Globals bound in device code.
__global__ void __launch_bounds__(256) k_gemm_l1(
    const float* __restrict__ x, const float* __restrict__ W1,
    const float* __restrict__ root1, const float* __restrict__ b1,
    int rowBlocks) {
    gemm_body(x, root1, W1, b1, g_h1, g_agg, 64, 1024, 64, 0, rowBlocks);
}

// Layer 2: [oacc | hw] = relu(h1) @ [root2 | W2cat] + b2 (oacc in g_cnt storage).
__global__ void __launch_bounds__(256) k_gemm_l2(
    const float* __restrict__ W2, const float* __restrict__ root2,
    const float* __restrict__ b2, int rowBlocks) {
    gemm_body(g_h1, root2, W2, b2, reinterpret_cast<float*>(g_cnt), g_agg,
              16, 256, 16, 1, rowBlocks);
}

// ---------------------------------------------------------------------------
__device__ __forceinline__ void red_add_v4(float* addr, float4 v) {
    asm volatile("red.global.add.v4.f32 [%0], {%1, %2, %3, %4};"
                 :: "l"(addr), "f"(v.x), "f"(v.y), "f"(v.z), "f"(v.w)
                 : "memory");
}

// 16 threads/edge: gather xw[src, r] (64 floats from g_agg), weight,
// RED into h1[dst] (L2-resident; holds the root term from the GEMM).
__global__ void k_scatter1(const int* __restrict__ src, const int* __restrict__ dst,
                           const int* __restrict__ et, int E) {
    long long gid = (long long)blockIdx.x * blockDim.x + threadIdx.x;
    int e = (int)(gid >> 4);
    int lane = (int)(gid & 15);
    if (e >= E) return;
    int s = __ldg(src + e), d = __ldg(dst + e), r = __ldg(et + e);
    float w = g_inv[r * N_NODES + d];
    float4 v = *reinterpret_cast<const float4*>(
        &g_agg[(size_t)s * KBIG + r * 64 + lane * 4]);
    red_add_v4(&g_h1[(size_t)d * D + lane * 4],
               make_float4(v.x * w, v.y * w, v.z * w, v.w * w));
}

// 4 threads/edge: gather hw[src, r] (16 floats from g_agg head), weight,
// RED into oacc[dst] = (float*)g_cnt (L2-resident; holds the root term).
__global__ void k_scatter2(const int* __restrict__ src, const int* __restrict__ dst,
                           const int* __restrict__ et, int E) {
    long long gid = (long long)blockIdx.x * blockDim.x + threadIdx.x;
    int e = (int)(gid >> 2);
    int lane = (int)(gid & 3);
    if (e >= E) return;
    int s = __ldg(src + e), d = __ldg(dst + e), r = __ldg(et + e);
    float w = g_inv[r * N_NODES + d];
    float4 v = *reinterpret_cast<const float4*>(
        &g_agg[(size_t)s * 256 + r * 16 + lane * 4]);
    red_add_v4(&reinterpret_cast<float*>(g_cnt)[(size_t)d * 16 + lane * 4],
               make_float4(v.x * w, v.y * w, v.z * w, v.w * w));
}

// relu + log_softmax over 16 classes; reads oacc (g_cnt storage), writes d_out
// with plain stores only. One thread per row.
__global__ void k_final(float* __restrict__ out) {
    int row = blockIdx.x * blockDim.x + threadIdx.x;
    if (row >= N_NODES) return;
    float v[16];
    const float4* p = reinterpret_cast<const float4*>(
        &reinterpret_cast<const float*>(g_cnt)[(size_t)row * 16]);
#pragma unroll
    for (int q = 0; q < 4; ++q) {
        float4 t = p[q];
        v[q * 4 + 0] = fmaxf(t.x, 0.f);
        v[q * 4 + 1] = fmaxf(t.y, 0.f);
        v[q * 4 + 2] = fmaxf(t.z, 0.f);
        v[q * 4 + 3] = fmaxf(t.w, 0.f);
    }
    float m = -1e30f;
#pragma unroll
    for (int j = 0; j < 16; ++j) m = fmaxf(m, v[j]);
    float s = 0.f;
#pragma unroll
    for (int j = 0; j < 16; ++j) s += expf(v[j] - m);
    float ls = m + logf(s);
    float4* q4 = reinterpret_cast<float4*>(&out[(size_t)row * 16]);
#pragma unroll
    for (int q = 0; q < 4; ++q)
        q4[q] = make_float4(v[q * 4 + 0] - ls, v[q * 4 + 1] - ls,
                            v[q * 4 + 2] - ls, v[q * 4 + 3] - ls);
}

// ---------------------------------------------------------------------------
extern "C" void kernel_launch(void* const* d_in, const int* in_sizes, int n_in,
                              void* d_out, int out_size) {
    const float* x     = (const float*)d_in[0];
    const int*   ei    = (const int*)d_in[1];
    const int*   et    = (const int*)d_in[2];
    const float* W1    = (const float*)d_in[3];
    const float* root1 = (const float*)d_in[4];
    const float* b1    = (const float*)d_in[5];
    const float* W2    = (const float*)d_in[6];
    const float* root2 = (const float*)d_in[7];
    const float* b2    = (const float*)d_in[8];
    float* out = (float*)d_out;

    const int E = in_sizes[2];
    const int* src = ei;
    const int* dst = ei + E;

    const int t = 256;
    const int gRN = (R * N_NODES + t - 1) / t;
    const int rowBlocks = (N_NODES + 63) / 64;
    const int gS1 = (int)(((long long)E * 16 + t - 1) / t);
    const int gS2 = (int)(((long long)E * 4 + t - 1) / t);

    // counts + inverse (shared by both layers); g_cnt is dead after k_inv
    k_zero_cnt<<<gRN, t>>>();
    k_count<<<(E + t - 1) / t, t>>>(dst, et, E);
    k_inv<<<gRN, t>>>();

    // layer 1: [h1 | xw] = x @ [root1 | W1cat] + b1; scatter messages into h1
    k_gemm_l1<<<rowBlocks * 17, t>>>(x, W1, root1, b1, rowBlocks);
    k_scatter1<<<gS1, t>>>(src, dst, et, E);

    // layer 2: [oacc | hw] = relu(h1) @ [root2 | W2cat] + b2 (oacc in g_cnt)
    k_gemm_l2<<<rowBlocks * 5, t>>>(W2, root2, b2, rowBlocks);
    k_scatter2<<<gS2, t>>>(src, dst, et, E);
    k_final<<<(N_NODES + t - 1) / t, t>>>(out);
}

// round 14
// speedup vs baseline: 1.9648x; 1.1787x over previous
#include <cuda_runtime.h>
#include <cuda_bf16.h>
#include <math.h>
#include <stdint.h>

// ---------------------------------------------------------------------------
// RGCN 2-layer, gather-side restructuring.
// HARD RULE (empirical): __device__ globals must NEVER be referenced from
// host code; they are bound inside __global__ wrappers in device code only.
//
//   [h1 | xw] = x @ [root1 | W1cat] (+b1)    (bf16x3 mma GEMM; xw -> g_agg)
//   h1[dst]  += xw[src, r] * inv[r,dst]      (RED.v4 into L2-resident g_h1)
//   [oacc | hw] = relu(h1) @ [root2 | W2cat] (+b2)  (oacc -> g_cnt storage)
//   oacc[dst] += hw[src, r] * inv[r,dst]     (RED.v4 into L2-resident oacc)
//   d_out = log_softmax(relu(oacc))          (plain stores, k_final only)
//
// R14 fix vs R13: NC uses CEILING division (272/64 -> 5, not 4); R13 silently
// dropped relation 15's hw columns in layer 2.
// ---------------------------------------------------------------------------

namespace {
constexpr int N_NODES = 100000;
constexpr int R = 16;
constexpr int D = 64;
constexpr int KBIG = R * D;  // 1024
constexpr int SEGS = 128;    // row-segments per column block
}

__device__ int   g_cnt[R * N_NODES];
__device__ float g_inv[R * N_NODES];
__device__ float g_agg[(size_t)N_NODES * KBIG];
__device__ float g_h1[(size_t)N_NODES * D];

// ---------------------------------------------------------------------------
__global__ void k_zero_cnt() {
    int i = blockIdx.x * blockDim.x + threadIdx.x;
    if (i < R * N_NODES) g_cnt[i] = 0;
}

__global__ void k_count(const int* __restrict__ dst, const int* __restrict__ et, int E) {
    int i = blockIdx.x * blockDim.x + threadIdx.x;
    if (i < E) atomicAdd(&g_cnt[et[i] * N_NODES + dst[i]], 1);
}

__global__ void k_inv() {
    int i = blockIdx.x * blockDim.x + threadIdx.x;
    if (i < R * N_NODES) {
        int c = g_cnt[i];
        g_inv[i] = 1.0f / (float)(c > 0 ? c : 1);
    }
}

// ---------------------------------------------------------------------------
// bf16 helpers: pack (x,y) into bf16x2 hi word + residual lo word.
// ---------------------------------------------------------------------------
__device__ __forceinline__ uint32_t bf2_split(float x, float y, uint32_t& lo_out) {
    __nv_bfloat162 h = __floats2bfloat162_rn(x, y);
    float2 hf = __bfloat1622float2(h);
    __nv_bfloat162 l = __floats2bfloat162_rn(x - hf.x, y - hf.y);
    lo_out = *reinterpret_cast<uint32_t*>(&l);
    return *reinterpret_cast<uint32_t*>(&h);
}

__device__ __forceinline__ void mma_bf16(float* c, const uint32_t* a, const uint32_t* b) {
    asm volatile(
        "mma.sync.aligned.m16n8k16.row.col.f32.bf16.bf16.f32 "
        "{%0,%1,%2,%3}, {%4,%5,%6,%7}, {%8,%9}, {%0,%1,%2,%3};"
        : "+f"(c[0]), "+f"(c[1]), "+f"(c[2]), "+f"(c[3])
        : "r"(a[0]), "r"(a[1]), "r"(a[2]), "r"(a[3]), "r"(b[0]), "r"(b[1]));
}

// ---------------------------------------------------------------------------
// Persistent fused GEMM body:
//   C[N x (d1+d2)] = A[N x 64] @ [root(64 x d1) | Wcat(64 x d2)]
// Root cols (+bias) -> outRoot (row stride d1); Wcat cols -> outW (stride d2).
// Wcat column w maps to W[(w/dout)*64*dout + k*dout + (w%dout)]  (W is (R,64,dout)).
// Grid = NC * SEGS (1-D), NC = ceil((d1+d2)/64). Block: cb = bid % NC, walks
// row tiles rb = bid/NC, += SEGS. B tile loaded+split once; A register-prefetched.
// BM=64, BN=64, K=64. 256 threads, 8 warps (4m x 2n), warp tile 16x32.
// Smem pair layout: uint2{hi bf16x2, lo bf16x2}, stride 36 (conflict-free LDS).
// ---------------------------------------------------------------------------
namespace {
constexpr int SP = 36;
}

__device__ __forceinline__ void gemm_body(
    const float* __restrict__ A, const float* __restrict__ root,
    const float* __restrict__ W, const float* __restrict__ bias,
    float* __restrict__ outRoot, float* __restrict__ outW,
    int d1, int d2, int dout, int reluA, int rowBlocks) {
    __shared__ uint2 Ax[64 * SP];   // 18.4 KB
    __shared__ uint2 Bx[64 * SP];   // 18.4 KB

    const int tid = threadIdx.x;
    const int NC = (d1 + d2 + 63) / 64;    // compile-time (17 or 5) — CEILING
    const int cb = blockIdx.x % NC;
    const int seg = blockIdx.x / NC;       // 0..SEGS-1
    const int dtot = d1 + d2;

    // ---- load B tile ONCE (column-fast / coalesced), split, transpose ----
#pragma unroll
    for (int i = 0; i < 8; ++i) {
        int idx = tid + i * 256;          // p * 64 + c  (c fast -> coalesced)
        int p = idx >> 6, c = idx & 63;
        int gc = cb * 64 + c;
        int k0 = p * 2;
        float f0 = 0.f, f1 = 0.f;
        if (gc < d1) {
            f0 = root[(size_t)k0 * d1 + gc];
            f1 = root[(size_t)(k0 + 1) * d1 + gc];
        } else if (gc < dtot) {
            int w = gc - d1;
            int r = w / dout, j = w - r * dout;
            f0 = W[((size_t)r * 64 + k0) * dout + j];
            f1 = W[((size_t)r * 64 + k0 + 1) * dout + j];
        }
        uint32_t lo;
        uint32_t hi = bf2_split(f0, f1, lo);
        Bx[c * SP + p] = make_uint2(hi, lo);
    }

    const int wid = tid >> 5, lane = tid & 31;
    const int g = lane >> 2, tg = lane & 3;
    const int wm = (wid & 3) * 16;    // warp row offset (4 warps in m)
    const int wn = (wid >> 2) * 32;   // warp col offset (2 warps in n)
    const int arow = tid >> 4, ac4 = tid & 15;   // this thread's A-load slot

    // ---- prefetch first A tile into registers ----
    float4 pref[4];
    {
        int rb = seg;
#pragma unroll
        for (int i = 0; i < 4; ++i) {
            int grow = rb * 64 + arow + i * 16;
            pref[i] = make_float4(0.f, 0.f, 0.f, 0.f);
            if (rb < rowBlocks && grow < N_NODES)
                pref[i] = reinterpret_cast<const float4*>(A)[(size_t)grow * 16 + ac4];
        }
    }

    for (int rb = seg; rb < rowBlocks; rb += SEGS) {
        // ---- store prefetched A tile to smem (split to bf16 hi/lo) ----
#pragma unroll
        for (int i = 0; i < 4; ++i) {
            float4 v = pref[i];
            if (reluA) {
                v.x = fmaxf(v.x, 0.f); v.y = fmaxf(v.y, 0.f);
                v.z = fmaxf(v.z, 0.f); v.w = fmaxf(v.w, 0.f);
            }
            uint32_t l01, l23;
            uint32_t h01 = bf2_split(v.x, v.y, l01);
            uint32_t h23 = bf2_split(v.z, v.w, l23);
            *reinterpret_cast<uint4*>(&Ax[(arow + i * 16) * SP + 2 * ac4]) =
                make_uint4(h01, l01, h23, l23);
        }
        __syncthreads();

        // ---- prefetch NEXT A tile (latency hidden under mma + epilogue) ----
        {
            int rbn = rb + SEGS;
#pragma unroll
            for (int i = 0; i < 4; ++i) {
                int grow = rbn * 64 + arow + i * 16;
                float4 v = make_float4(0.f, 0.f, 0.f, 0.f);
                if (rbn < rowBlocks && grow < N_NODES)
                    v = reinterpret_cast<const float4*>(A)[(size_t)grow * 16 + ac4];
                pref[i] = v;
            }
        }

        // ---- mma mainloop (identical to R12-verified mapping) ----
        float acc[4][4];
#pragma unroll
        for (int nt = 0; nt < 4; ++nt)
#pragma unroll
            for (int q = 0; q < 4; ++q) acc[nt][q] = 0.f;

#pragma unroll
        for (int ks = 0; ks < 4; ++ks) {
            const int p0 = ks * 8;            // pair offset (16 k per step)
            uint2 A0 = Ax[(wm + g)     * SP + p0 + tg];
            uint2 A1 = Ax[(wm + g + 8) * SP + p0 + tg];
            uint2 A2 = Ax[(wm + g)     * SP + p0 + tg + 4];
            uint2 A3 = Ax[(wm + g + 8) * SP + p0 + tg + 4];
            uint32_t ah[4] = {A0.x, A1.x, A2.x, A3.x};
            uint32_t al[4] = {A0.y, A1.y, A2.y, A3.y};
            uint32_t bh[4][2], bl[4][2];
#pragma unroll
            for (int nt = 0; nt < 4; ++nt) {
                int c0 = wn + nt * 8 + g;
                uint2 B0 = Bx[c0 * SP + p0 + tg];
                uint2 B1 = Bx[c0 * SP + p0 + tg + 4];
                bh[nt][0] = B0.x; bh[nt][1] = B1.x;
                bl[nt][0] = B0.y; bl[nt][1] = B1.y;
            }
#pragma unroll
            for (int nt = 0; nt < 4; ++nt) {
                mma_bf16(acc[nt], ah, bh[nt]);   // hi*hi
                mma_bf16(acc[nt], ah, bl[nt]);   // hi*lo
                mma_bf16(acc[nt], al, bh[nt]);   // lo*hi
            }
        }

        // ---- epilogue: root cols (+bias) -> outRoot; W cols -> outW ----
#pragma unroll
        for (int nt = 0; nt < 4; ++nt) {
            int col = wn + nt * 8 + 2 * tg;
            int gc = cb * 64 + col;
            int r0 = rb * 64 + wm + g;
            int r1 = r0 + 8;
            float2 v0 = make_float2(acc[nt][0], acc[nt][1]);
            float2 v1 = make_float2(acc[nt][2], acc[nt][3]);
            if (gc < d1) {
                float bx = bias[gc], by = bias[gc + 1];
                v0.x += bx; v0.y += by; v1.x += bx; v1.y += by;
                if (r0 < N_NODES)
                    *reinterpret_cast<float2*>(&outRoot[(size_t)r0 * d1 + gc]) = v0;
                if (r1 < N_NODES)
                    *reinterpret_cast<float2*>(&outRoot[(size_t)r1 * d1 + gc]) = v1;
            } else if (gc < dtot) {
                int w = gc - d1;
                if (r0 < N_NODES)
                    *reinterpret_cast<float2*>(&outW[(size_t)r0 * d2 + w]) = v0;
                if (r1 < N_NODES)
                    *reinterpret_cast<float2*>(&outW[(size_t)r1 * d2 + w]) = v1;
            }
        }
        __syncthreads();   // Ax consumers done before next iteration's STS
    }
}

// Layer 1: [h1 | xw] = x @ [root1 | W1cat] + b1. Globals bound in device code.
__global__ void __launch_bounds__(256) k_gemm_l1(
    const float* __restrict__ x, const float* __restrict__ W1,
    const float* __restrict__ root1, const float* __restrict__ b1,
    int rowBlocks) {
    gemm_body(x, root1, W1, b1, g_h1, g_agg, 64, 1024, 64, 0, rowBlocks);
}

// Layer 2: [oacc | hw] = relu(h1) @ [root2 | W2cat] + b2 (oacc in g_cnt storage).
__global__ void __launch_bounds__(256) k_gemm_l2(
    const float* __restrict__ W2, const float* __restrict__ root2,
    const float* __restrict__ b2, int rowBlocks) {
    gemm_body(g_h1, root2, W2, b2, reinterpret_cast<float*>(g_cnt), g_agg,
              16, 256, 16, 1, rowBlocks);
}

// ---------------------------------------------------------------------------
__device__ __forceinline__ void red_add_v4(float* addr, float4 v) {
    asm volatile("red.global.add.v4.f32 [%0], {%1, %2, %3, %4};"
                 :: "l"(addr), "f"(v.x), "f"(v.y), "f"(v.z), "f"(v.w)
                 : "memory");
}

// 16 threads/edge: gather xw[src, r] (64 floats from g_agg), weight,
// RED into h1[dst] (L2-resident; holds the root term from the GEMM).
__global__ void k_scatter1(const int* __restrict__ src, const int* __restrict__ dst,
                           const int* __restrict__ et, int E) {
    long long gid = (long long)blockIdx.x * blockDim.x + threadIdx.x;
    int e = (int)(gid >> 4);
    int lane = (int)(gid & 15);
    if (e >= E) return;
    int s = __ldg(src + e), d = __ldg(dst + e), r = __ldg(et + e);
    float w = g_inv[r * N_NODES + d];
    float4 v = *reinterpret_cast<const float4*>(
        &g_agg[(size_t)s * KBIG + r * 64 + lane * 4]);
    red_add_v4(&g_h1[(size_t)d * D + lane * 4],
               make_float4(v.x * w, v.y * w, v.z * w, v.w * w));
}

// 4 threads/edge: gather hw[src, r] (16 floats from g_agg head), weight,
// RED into oacc[dst] = (float*)g_cnt (L2-resident; holds the root term).
__global__ void k_scatter2(const int* __restrict__ src, const int* __restrict__ dst,
                           const int* __restrict__ et, int E) {
    long long gid = (long long)blockIdx.x * blockDim.x + threadIdx.x;
    int e = (int)(gid >> 2);
    int lane = (int)(gid & 3);
    if (e >= E) return;
    int s = __ldg(src + e), d = __ldg(dst + e), r = __ldg(et + e);
    float w = g_inv[r * N_NODES + d];
    float4 v = *reinterpret_cast<const float4*>(
        &g_agg[(size_t)s * 256 + r * 16 + lane * 4]);
    red_add_v4(&reinterpret_cast<float*>(g_cnt)[(size_t)d * 16 + lane * 4],
               make_float4(v.x * w, v.y * w, v.z * w, v.w * w));
}

// relu + log_softmax over 16 classes; reads oacc (g_cnt storage), writes d_out
// with plain stores only. One thread per row.
__global__ void k_final(float* __restrict__ out) {
    int row = blockIdx.x * blockDim.x + threadIdx.x;
    if (row >= N_NODES) return;
    float v[16];
    const float4* p = reinterpret_cast<const float4*>(
        &reinterpret_cast<const float*>(g_cnt)[(size_t)row * 16]);
#pragma unroll
    for (int q = 0; q < 4; ++q) {
        float4 t = p[q];
        v[q * 4 + 0] = fmaxf(t.x, 0.f);
        v[q * 4 + 1] = fmaxf(t.y, 0.f);
        v[q * 4 + 2] = fmaxf(t.z, 0.f);
        v[q * 4 + 3] = fmaxf(t.w, 0.f);
    }
    float m = -1e30f;
#pragma unroll
    for (int j = 0; j < 16; ++j) m = fmaxf(m, v[j]);
    float s = 0.f;
#pragma unroll
    for (int j = 0; j < 16; ++j) s += expf(v[j] - m);
    float ls = m + logf(s);
    float4* q4 = reinterpret_cast<float4*>(&out[(size_t)row * 16]);
#pragma unroll
    for (int q = 0; q < 4; ++q)
        q4[q] = make_float4(v[q * 4 + 0] - ls, v[q * 4 + 1] - ls,
                            v[q * 4 + 2] - ls, v[q * 4 + 3] - ls);
}

// ---------------------------------------------------------------------------
extern "C" void kernel_launch(void* const* d_in, const int* in_sizes, int n_in,
                              void* d_out, int out_size) {
    const float* x     = (const float*)d_in[0];
    const int*   ei    = (const int*)d_in[1];
    const int*   et    = (const int*)d_in[2];
    const float* W1    = (const float*)d_in[3];
    const float* root1 = (const float*)d_in[4];
    const float* b1    = (const float*)d_in[5];
    const float* W2    = (const float*)d_in[6];
    const float* root2 = (const float*)d_in[7];
    const float* b2    = (const float*)d_in[8];
    float* out = (float*)d_out;

    const int E = in_sizes[2];
    const int* src = ei;
    const int* dst = ei + E;

    const int t = 256;
    const int gRN = (R * N_NODES + t - 1) / t;
    const int rowBlocks = (N_NODES + 63) / 64;
    const int gS1 = (int)(((long long)E * 16 + t - 1) / t);
    const int gS2 = (int)(((long long)E * 4 + t - 1) / t);

    // counts + inverse (shared by both layers); g_cnt is dead after k_inv
    k_zero_cnt<<<gRN, t>>>();
    k_count<<<(E + t - 1) / t, t>>>(dst, et, E);
    k_inv<<<gRN, t>>>();

    // layer 1: [h1 | xw] = x @ [root1 | W1cat] + b1; scatter messages into h1
    k_gemm_l1<<<17 * SEGS, t>>>(x, W1, root1, b1, rowBlocks);
    k_scatter1<<<gS1, t>>>(src, dst, et, E);

    // layer 2: [oacc | hw] = relu(h1) @ [root2 | W2cat] + b2 (oacc in g_cnt)
    k_gemm_l2<<<5 * SEGS, t>>>(W2, root2, b2, rowBlocks);
    k_scatter2<<<gS2, t>>>(src, dst, et, E);
    k_final<<<(N_NODES + t - 1) / t, t>>>(out);
}

// round 15
// speedup vs baseline: 1.9649x; 1.0001x over previous
#include <cuda_runtime.h>
#include <cuda_bf16.h>
#include <cuda_fp16.h>
#include <math.h>
#include <stdint.h>

// ---------------------------------------------------------------------------
// RGCN 2-layer, gather-side restructuring.
// HARD RULE (empirical): __device__ globals must NEVER be referenced from
// host code; they are bound inside __global__ wrappers in device code only.
//
//   xsplit = bf16-hi/lo(x)                  (k_split_x, once)
//   [h1 | xw16] = x @ [root1 | W1cat] (+b1) (GEMM reads xsplit; xw -> fp16)
//   h1[dst]  += xw16[src, r] * inv[r,dst]   (RED.v4 into L2-resident g_h1)
//   hsplit = bf16-hi/lo(relu(h1))           (k_split_h1, once)
//   [oacc | hw] = relu(h1) @ [root2 | W2cat] (+b2)  (hw fp32 -> g_agg head)
//   oacc[dst] += hw[src, r] * inv[r,dst]    (oacc in g_cnt storage)
//   d_out = log_softmax(relu(oacc))         (plain stores, k_final only)
//
// g_agg byte map:  [0, 204.8MB)   xw fp16 (layer1) then hw fp32 (layer2)
//                  [204.8, 230.4) pre-split A (uint2 hi/lo pairs, 32/row)
// ---------------------------------------------------------------------------

namespace {
constexpr int N_NODES = 100000;
constexpr int R = 16;
constexpr int D = 64;
constexpr int KBIG = R * D;  // 1024
constexpr int SEGS = 128;    // row-segments per column block
}

__device__ int   g_cnt[R * N_NODES];
__device__ float g_inv[R * N_NODES];
__device__ float g_agg[(size_t)N_NODES * KBIG];
__device__ float g_h1[(size_t)N_NODES * D];

// Device-side region binding (never referenced from host).
__device__ __forceinline__ uint2* axs_ptr() {
    return reinterpret_cast<uint2*>(g_agg) + (size_t)N_NODES * 256;
}

// ---------------------------------------------------------------------------
__global__ void k_zero_cnt() {
    int i = blockIdx.x * blockDim.x + threadIdx.x;
    if (i < R * N_NODES) g_cnt[i] = 0;
}

__global__ void k_count(const int* __restrict__ dst, const int* __restrict__ et, int E) {
    int i = blockIdx.x * blockDim.x + threadIdx.x;
    if (i < E) atomicAdd(&g_cnt[et[i] * N_NODES + dst[i]], 1);
}

__global__ void k_inv() {
    int i = blockIdx.x * blockDim.x + threadIdx.x;
    if (i < R * N_NODES) {
        int c = g_cnt[i];
        g_inv[i] = 1.0f / (float)(c > 0 ? c : 1);
    }
}

// ---------------------------------------------------------------------------
// bf16 helpers: pack (x,y) into bf16x2 hi word + residual lo word.
// ---------------------------------------------------------------------------
__device__ __forceinline__ uint32_t bf2_split(float x, float y, uint32_t& lo_out) {
    __nv_bfloat162 h = __floats2bfloat162_rn(x, y);
    float2 hf = __bfloat1622float2(h);
    __nv_bfloat162 l = __floats2bfloat162_rn(x - hf.x, y - hf.y);
    lo_out = *reinterpret_cast<uint32_t*>(&l);
    return *reinterpret_cast<uint32_t*>(&h);
}

__device__ __forceinline__ void mma_bf16(float* c, const uint32_t* a, const uint32_t* b) {
    asm volatile(
        "mma.sync.aligned.m16n8k16.row.col.f32.bf16.bf16.f32 "
        "{%0,%1,%2,%3}, {%4,%5,%6,%7}, {%8,%9}, {%0,%1,%2,%3};"
        : "+f"(c[0]), "+f"(c[1]), "+f"(c[2]), "+f"(c[3])
        : "r"(a[0]), "r"(a[1]), "r"(a[2]), "r"(a[3]), "r"(b[0]), "r"(b[1]));
}

// ---------------------------------------------------------------------------
// Pre-split kernels: A rows -> packed uint2{hi,lo} pairs (32 per row).
// ---------------------------------------------------------------------------
__global__ void k_split_x(const float* __restrict__ x) {
    int i = blockIdx.x * blockDim.x + threadIdx.x;   // over N*16 float4s
    if (i >= N_NODES * 16) return;
    float4 v = reinterpret_cast<const float4*>(x)[i];
    uint32_t l01, l23;
    uint32_t h01 = bf2_split(v.x, v.y, l01);
    uint32_t h23 = bf2_split(v.z, v.w, l23);
    int row = i >> 4, c4 = i & 15;
    *reinterpret_cast<uint4*>(&axs_ptr()[(size_t)row * 32 + 2 * c4]) =
        make_uint4(h01, l01, h23, l23);
}

__global__ void k_split_h1() {
    int i = blockIdx.x * blockDim.x + threadIdx.x;   // over N*16 float4s
    if (i >= N_NODES * 16) return;
    float4 v = reinterpret_cast<const float4*>(g_h1)[i];
    v.x = fmaxf(v.x, 0.f); v.y = fmaxf(v.y, 0.f);
    v.z = fmaxf(v.z, 0.f); v.w = fmaxf(v.w, 0.f);
    uint32_t l01, l23;
    uint32_t h01 = bf2_split(v.x, v.y, l01);
    uint32_t h23 = bf2_split(v.z, v.w, l23);
    int row = i >> 4, c4 = i & 15;
    *reinterpret_cast<uint4*>(&axs_ptr()[(size_t)row * 32 + 2 * c4]) =
        make_uint4(h01, l01, h23, l23);
}

// ---------------------------------------------------------------------------
// Persistent fused GEMM body (A pre-split):
//   C[N x (d1+d2)] = A[N x 64] @ [root(64 x d1) | Wcat(64 x d2)]
// Root cols (+bias) -> outRoot (fp32, stride d1). Wcat cols -> outWh (fp16)
// when halfW, else outWf (fp32), stride d2.
// Wcat column w maps to W[(w/dout)*64*dout + k*dout + (w%dout)]  (W is (R,64,dout)).
// Grid = NC * SEGS, NC = ceil((d1+d2)/64). cb = bid % NC; rb walks seg += SEGS.
// BM=64, BN=64, K=64. 256 threads, 8 warps (4m x 2n), warp tile 16x32.
// Smem pair layout: uint2{hi bf16x2, lo bf16x2}, stride 36 (conflict-free LDS).
// ---------------------------------------------------------------------------
namespace {
constexpr int SP = 36;
}

__device__ __forceinline__ void gemm_body(
    const uint2* __restrict__ Aps, const float* __restrict__ root,
    const float* __restrict__ W, const float* __restrict__ bias,
    float* __restrict__ outRoot, float* __restrict__ outWf,
    __half* __restrict__ outWh,
    int d1, int d2, int dout, int halfW, int rowBlocks) {
    __shared__ uint2 Ax[64 * SP];   // 18.4 KB
    __shared__ uint2 Bx[64 * SP];   // 18.4 KB

    const int tid = threadIdx.x;
    const int NC = (d1 + d2 + 63) / 64;    // compile-time (17 or 5), ceiling
    const int cb = blockIdx.x % NC;
    const int seg = blockIdx.x / NC;       // 0..SEGS-1
    const int dtot = d1 + d2;

    // ---- load B tile ONCE (column-fast / coalesced), split, transpose ----
#pragma unroll
    for (int i = 0; i < 8; ++i) {
        int idx = tid + i * 256;          // p * 64 + c  (c fast -> coalesced)
        int p = idx >> 6, c = idx & 63;
        int gc = cb * 64 + c;
        int k0 = p * 2;
        float f0 = 0.f, f1 = 0.f;
        if (gc < d1) {
            f0 = root[(size_t)k0 * d1 + gc];
            f1 = root[(size_t)(k0 + 1) * d1 + gc];
        } else if (gc < dtot) {
            int w = gc - d1;
            int r = w / dout, j = w - r * dout;
            f0 = W[((size_t)r * 64 + k0) * dout + j];
            f1 = W[((size_t)r * 64 + k0 + 1) * dout + j];
        }
        uint32_t lo;
        uint32_t hi = bf2_split(f0, f1, lo);
        Bx[c * SP + p] = make_uint2(hi, lo);
    }

    const int wid = tid >> 5, lane = tid & 31;
    const int g = lane >> 2, tg = lane & 3;
    const int wm = (wid & 3) * 16;    // warp row offset (4 warps in m)
    const int wn = (wid >> 2) * 32;   // warp col offset (2 warps in n)
    const int arow = tid >> 4, ac4 = tid & 15;   // this thread's A-load slot

    // ---- prefetch first A tile (already split) ----
    uint4 pref[4];
    {
        int rb = seg;
#pragma unroll
        for (int i = 0; i < 4; ++i) {
            int grow = rb * 64 + arow + i * 16;
            pref[i] = make_uint4(0u, 0u, 0u, 0u);
            if (rb < rowBlocks && grow < N_NODES)
                pref[i] = *reinterpret_cast<const uint4*>(
                    &Aps[(size_t)grow * 32 + 2 * ac4]);
        }
    }

    for (int rb = seg; rb < rowBlocks; rb += SEGS) {
        // ---- store prefetched A tile to smem (pure STS.128) ----
#pragma unroll
        for (int i = 0; i < 4; ++i)
            *reinterpret_cast<uint4*>(&Ax[(arow + i * 16) * SP + 2 * ac4]) = pref[i];
        __syncthreads();

        // ---- prefetch NEXT A tile (latency hidden under mma + epilogue) ----
        {
            int rbn = rb + SEGS;
#pragma unroll
            for (int i = 0; i < 4; ++i) {
                int grow = rbn * 64 + arow + i * 16;
                uint4 v = make_uint4(0u, 0u, 0u, 0u);
                if (rbn < rowBlocks && grow < N_NODES)
                    v = *reinterpret_cast<const uint4*>(
                        &Aps[(size_t)grow * 32 + 2 * ac4]);
                pref[i] = v;
            }
        }

        // ---- mma mainloop (identical to R12/R14-verified mapping) ----
        float acc[4][4];
#pragma unroll
        for (int nt = 0; nt < 4; ++nt)
#pragma unroll
            for (int q = 0; q < 4; ++q) acc[nt][q] = 0.f;

#pragma unroll
        for (int ks = 0; ks < 4; ++ks) {
            const int p0 = ks * 8;            // pair offset (16 k per step)
            uint2 A0 = Ax[(wm + g)     * SP + p0 + tg];
            uint2 A1 = Ax[(wm + g + 8) * SP + p0 + tg];
            uint2 A2 = Ax[(wm + g)     * SP + p0 + tg + 4];
            uint2 A3 = Ax[(wm + g + 8) * SP + p0 + tg + 4];
            uint32_t ah[4] = {A0.x, A1.x, A2.x, A3.x};
            uint32_t al[4] = {A0.y, A1.y, A2.y, A3.y};
            uint32_t bh[4][2], bl[4][2];
#pragma unroll
            for (int nt = 0; nt < 4; ++nt) {
                int c0 = wn + nt * 8 + g;
                uint2 B0 = Bx[c0 * SP + p0 + tg];
                uint2 B1 = Bx[c0 * SP + p0 + tg + 4];
                bh[nt][0] = B0.x; bh[nt][1] = B1.x;
                bl[nt][0] = B0.y; bl[nt][1] = B1.y;
            }
#pragma unroll
            for (int nt = 0; nt < 4; ++nt) {
                mma_bf16(acc[nt], ah, bh[nt]);   // hi*hi
                mma_bf16(acc[nt], ah, bl[nt]);   // hi*lo
                mma_bf16(acc[nt], al, bh[nt]);   // lo*hi
            }
        }

        // ---- epilogue: root cols (+bias) fp32; W cols fp16 or fp32 ----
#pragma unroll
        for (int nt = 0; nt < 4; ++nt) {
            int col = wn + nt * 8 + 2 * tg;
            int gc = cb * 64 + col;
            int r0 = rb * 64 + wm + g;
            int r1 = r0 + 8;
            float2 v0 = make_float2(acc[nt][0], acc[nt][1]);
            float2 v1 = make_float2(acc[nt][2], acc[nt][3]);
            if (gc < d1) {
                float bx = bias[gc], by = bias[gc + 1];
                v0.x += bx; v0.y += by; v1.x += bx; v1.y += by;
                if (r0 < N_NODES)
                    *reinterpret_cast<float2*>(&outRoot[(size_t)r0 * d1 + gc]) = v0;
                if (r1 < N_NODES)
                    *reinterpret_cast<float2*>(&outRoot[(size_t)r1 * d1 + gc]) = v1;
            } else if (gc < dtot) {
                int w = gc - d1;
                if (halfW) {
                    if (r0 < N_NODES)
                        *reinterpret_cast<__half2*>(&outWh[(size_t)r0 * d2 + w]) =
                            __floats2half2_rn(v0.x, v0.y);
                    if (r1 < N_NODES)
                        *reinterpret_cast<__half2*>(&outWh[(size_t)r1 * d2 + w]) =
                            __floats2half2_rn(v1.x, v1.y);
                } else {
                    if (r0 < N_NODES)
                        *reinterpret_cast<float2*>(&outWf[(size_t)r0 * d2 + w]) = v0;
                    if (r1 < N_NODES)
                        *reinterpret_cast<float2*>(&outWf[(size_t)r1 * d2 + w]) = v1;
                }
            }
        }
        __syncthreads();   // Ax consumers done before next iteration's STS
    }
}

// Layer 1: [h1 | xw16] = x @ [root1 | W1cat] + b1. Globals bound in device code.
__global__ void __launch_bounds__(256) k_gemm_l1(
    const float* __restrict__ W1, const float* __restrict__ root1,
    const float* __restrict__ b1, int rowBlocks) {
    gemm_body(axs_ptr(), root1, W1, b1, g_h1, nullptr,
              reinterpret_cast<__half*>(g_agg), 64, 1024, 64, 1, rowBlocks);
}

// Layer 2: [oacc | hw] = relu(h1) @ [root2 | W2cat] + b2 (oacc in g_cnt storage,
// hw fp32 in g_agg head, A pre-split by k_split_h1).
__global__ void __launch_bounds__(256) k_gemm_l2(
    const float* __restrict__ W2, const float* __restrict__ root2,
    const float* __restrict__ b2, int rowBlocks) {
    gemm_body(axs_ptr(), root2, W2, b2, reinterpret_cast<float*>(g_cnt),
              g_agg, nullptr, 16, 256, 16, 0, rowBlocks);
}

// ---------------------------------------------------------------------------
__device__ __forceinline__ void red_add_v4(float* addr, float4 v) {
    asm volatile("red.global.add.v4.f32 [%0], {%1, %2, %3, %4};"
                 :: "l"(addr), "f"(v.x), "f"(v.y), "f"(v.z), "f"(v.w)
                 : "memory");
}

// 8 threads/edge: gather 8 fp16 of xw[src, r], weight, RED 8 floats into h1[dst].
__global__ void k_scatter1(const int* __restrict__ src, const int* __restrict__ dst,
                           const int* __restrict__ et, int E) {
    long long gid = (long long)blockIdx.x * blockDim.x + threadIdx.x;
    int e = (int)(gid >> 3);
    int lane = (int)(gid & 7);
    if (e >= E) return;
    int s = __ldg(src + e), d = __ldg(dst + e), r = __ldg(et + e);
    float w = g_inv[r * N_NODES + d];
    const __half* xwh = reinterpret_cast<const __half*>(g_agg);
    uint4 raw = *reinterpret_cast<const uint4*>(
        &xwh[(size_t)s * 1024 + r * 64 + lane * 8]);
    float2 f0 = __half22float2(*reinterpret_cast<__half2*>(&raw.x));
    float2 f1 = __half22float2(*reinterpret_cast<__half2*>(&raw.y));
    float2 f2 = __half22float2(*reinterpret_cast<__half2*>(&raw.z));
    float2 f3 = __half22float2(*reinterpret_cast<__half2*>(&raw.w));
    float* base = &g_h1[(size_t)d * D + lane * 8];
    red_add_v4(base,     make_float4(f0.x * w, f0.y * w, f1.x * w, f1.y * w));
    red_add_v4(base + 4, make_float4(f2.x * w, f2.y * w, f3.x * w, f3.y * w));
}

// 4 threads/edge: gather hw[src, r] (16 fp32 from g_agg head), weight,
// RED into oacc[dst] = (float*)g_cnt (L2-resident; holds the root term).
__global__ void k_scatter2(const int* __restrict__ src, const int* __restrict__ dst,
                           const int* __restrict__ et, int E) {
    long long gid = (long long)blockIdx.x * blockDim.x + threadIdx.x;
    int e = (int)(gid >> 2);
    int lane = (int)(gid & 3);
    if (e >= E) return;
    int s = __ldg(src + e), d = __ldg(dst + e), r = __ldg(et + e);
    float w = g_inv[r * N_NODES + d];
    float4 v = *reinterpret_cast<const float4*>(
        &g_agg[(size_t)s * 256 + r * 16 + lane * 4]);
    red_add_v4(&reinterpret_cast<float*>(g_cnt)[(size_t)d * 16 + lane * 4],
               make_float4(v.x * w, v.y * w, v.z * w, v.w * w));
}

// relu + log_softmax over 16 classes; reads oacc (g_cnt storage), writes d_out
// with plain stores only. One thread per row.
__global__ void k_final(float* __restrict__ out) {
    int row = blockIdx.x * blockDim.x + threadIdx.x;
    if (row >= N_NODES) return;
    float v[16];
    const float4* p = reinterpret_cast<const float4*>(
        &reinterpret_cast<const float*>(g_cnt)[(size_t)row * 16]);
#pragma unroll
    for (int q = 0; q < 4; ++q) {
        float4 t = p[q];
        v[q * 4 + 0] = fmaxf(t.x, 0.f);
        v[q * 4 + 1] = fmaxf(t.y, 0.f);
        v[q * 4 + 2] = fmaxf(t.z, 0.f);
        v[q * 4 + 3] = fmaxf(t.w, 0.f);
    }
    float m = -1e30f;
#pragma unroll
    for (int j = 0; j < 16; ++j) m = fmaxf(m, v[j]);
    float s = 0.f;
#pragma unroll
    for (int j = 0; j < 16; ++j) s += expf(v[j] - m);
    float ls = m + logf(s);
    float4* q4 = reinterpret_cast<float4*>(&out[(size_t)row * 16]);
#pragma unroll
    for (int q = 0; q < 4; ++q)
        q4[q] = make_float4(v[q * 4 + 0] - ls, v[q * 4 + 1] - ls,
                            v[q * 4 + 2] - ls, v[q * 4 + 3] - ls);
}

// ---------------------------------------------------------------------------
extern "C" void kernel_launch(void* const* d_in, const int* in_sizes, int n_in,
                              void* d_out, int out_size) {
    const float* x     = (const float*)d_in[0];
    const int*   ei    = (const int*)d_in[1];
    const int*   et    = (const int*)d_in[2];
    const float* W1    = (const float*)d_in[3];
    const float* root1 = (const float*)d_in[4];
    const float* b1    = (const float*)d_in[5];
    const float* W2    = (const float*)d_in[6];
    const float* root2 = (const float*)d_in[7];
    const float* b2    = (const float*)d_in[8];
    float* out = (float*)d_out;

    const int E = in_sizes[2];
    const int* src = ei;
    const int* dst = ei + E;

    const int t = 256;
    const int gRN = (R * N_NODES + t - 1) / t;
    const int rowBlocks = (N_NODES + 63) / 64;
    const int gSplit = (N_NODES * 16 + t - 1) / t;
    const int gS1 = (int)(((long long)E * 8 + t - 1) / t);
    const int gS2 = (int)(((long long)E * 4 + t - 1) / t);

    // counts + inverse (shared by both layers); g_cnt is dead after k_inv
    k_zero_cnt<<<gRN, t>>>();
    k_count<<<(E + t - 1) / t, t>>>(dst, et, E);
    k_inv<<<gRN, t>>>();

    // layer 1: pre-split x, GEMM, scatter fp16 messages into h1
    k_split_x<<<gSplit, t>>>(x);
    k_gemm_l1<<<17 * SEGS, t>>>(W1, root1, b1, rowBlocks);
    k_scatter1<<<gS1, t>>>(src, dst, et, E);

    // layer 2: pre-split relu(h1), GEMM (oacc in g_cnt, hw fp32), scatter, final
    k_split_h1<<<gSplit, t>>>();
    k_gemm_l2<<<5 * SEGS, t>>>(W2, root2, b2, rowBlocks);
    k_scatter2<<<gS2, t>>>(src, dst, et, E);
    k_final<<<(N_NODES + t - 1) / t, t>>>(out);
}